// round 2
// baseline (speedup 1.0000x reference)
#include <cuda_runtime.h>
#include <math.h>

#define BB 64
#define SS 1024
#define II 256
#define HH 512
#define GH 2048   // 4*H
#define NB 128    // persistent blocks for recurrence

// Scratch (static __device__ allowed; no runtime allocs).
__device__ float   g_xg[134217728];   // [S][2048][64]  x-side gate preacts (+bi), 512MB
__device__ float   g_h[2][HH * BB];   // [j][b] double-buffered hidden state
__device__ unsigned g_bar;            // grid barrier counter

__global__ void reset_bar_k() { g_bar = 0u; }

// ---------------------------------------------------------------------------
// Kernel 1: x_gates[t][g][b] = sum_i x[b][t][i] * Wi[g][i] + bi[g]
// grid (32 gate-tiles of 64, 1024 timesteps), 256 threads, 64KB dynamic smem.
// ---------------------------------------------------------------------------
__global__ void __launch_bounds__(256) gemm_in(
    const float* __restrict__ x,
    const float* __restrict__ W0, const float* __restrict__ W1,
    const float* __restrict__ W2, const float* __restrict__ W3,
    const float* __restrict__ bi0, const float* __restrict__ bi1,
    const float* __restrict__ bi2, const float* __restrict__ bi3)
{
    extern __shared__ float sm[];
    float* xs = sm;            // [128 i][64 b]
    float* ws = sm + 128 * 64; // [128 i][64 g]

    const int t   = blockIdx.y;
    const int gt  = blockIdx.x;          // 0..31 (64 gate rows each)
    const int tid = threadIdx.x;
    const int gate = gt >> 3;            // 8 tiles per gate (512/64)
    const float* W  = gate == 0 ? W0 : gate == 1 ? W1 : gate == 2 ? W2 : W3;
    const float* bi = gate == 0 ? bi0 : gate == 1 ? bi1 : gate == 2 ? bi2 : bi3;
    const int u0 = (gt & 7) * 64;        // unit offset inside this gate

    const int g0 = (tid & 15) * 4;
    const int b0 = (tid >> 4) * 4;
    float acc[4][4] = {};

    for (int kc = 0; kc < 2; ++kc) {
        const int koff = kc * 128;
        // load x chunk, transpose to [i][b]
        for (int idx = tid; idx < 2048; idx += 256) {
            const int row = idx >> 5, q = idx & 31;
            const float4 v = *(const float4*)(x + ((size_t)row * SS + t) * II + koff + q * 4);
            const int i0 = q * 4;
            xs[(i0 + 0) * 64 + row] = v.x;
            xs[(i0 + 1) * 64 + row] = v.y;
            xs[(i0 + 2) * 64 + row] = v.z;
            xs[(i0 + 3) * 64 + row] = v.w;
        }
        // load Wi chunk, transpose to [i][g]
        for (int idx = tid; idx < 2048; idx += 256) {
            const int row = idx >> 5, q = idx & 31;
            const float4 v = *(const float4*)(W + (size_t)(u0 + row) * II + koff + q * 4);
            const int i0 = q * 4;
            ws[(i0 + 0) * 64 + row] = v.x;
            ws[(i0 + 1) * 64 + row] = v.y;
            ws[(i0 + 2) * 64 + row] = v.z;
            ws[(i0 + 3) * 64 + row] = v.w;
        }
        __syncthreads();
        #pragma unroll 4
        for (int i = 0; i < 128; ++i) {
            const float4 wv = *(const float4*)(ws + i * 64 + g0);
            const float4 xv = *(const float4*)(xs + i * 64 + b0);
            acc[0][0] += wv.x * xv.x; acc[0][1] += wv.x * xv.y;
            acc[0][2] += wv.x * xv.z; acc[0][3] += wv.x * xv.w;
            acc[1][0] += wv.y * xv.x; acc[1][1] += wv.y * xv.y;
            acc[1][2] += wv.y * xv.z; acc[1][3] += wv.y * xv.w;
            acc[2][0] += wv.z * xv.x; acc[2][1] += wv.z * xv.y;
            acc[2][2] += wv.z * xv.z; acc[2][3] += wv.z * xv.w;
            acc[3][0] += wv.w * xv.x; acc[3][1] += wv.w * xv.y;
            acc[3][2] += wv.w * xv.z; acc[3][3] += wv.w * xv.w;
        }
        __syncthreads();
    }

    const size_t obase = (size_t)t * GH * BB + (size_t)(gate * HH + u0 + g0) * BB + b0;
    #pragma unroll
    for (int gi = 0; gi < 4; ++gi) {
        const float bv = bi[u0 + g0 + gi];
        const float4 o = make_float4(acc[gi][0] + bv, acc[gi][1] + bv,
                                     acc[gi][2] + bv, acc[gi][3] + bv);
        *(float4*)(g_xg + obase + (size_t)gi * BB) = o;
    }
}

// ---------------------------------------------------------------------------
// Kernel 2: persistent recurrence. 128 blocks x 256 threads, 1 block/SM.
// Block owns hidden units [4*bid, 4*bid+4): their 16 Wh gate rows stay in
// shared, their cell state stays in shared. h is exchanged via global double
// buffer + atomic grid barrier each step.
// ---------------------------------------------------------------------------
__global__ void __launch_bounds__(256, 1) lstm_rec(
    const float* __restrict__ Wh0, const float* __restrict__ Wh1,
    const float* __restrict__ Wh2, const float* __restrict__ Wh3,
    const float* __restrict__ bh0, const float* __restrict__ bh1,
    const float* __restrict__ bh2, const float* __restrict__ bh3,
    float* __restrict__ out)
{
    extern __shared__ float sm[];
    float* h_sh  = sm;            // [512 k][64 b]   32768
    float* W_sh  = sm + 32768;    // [512 k][16 r]    8192
    float* red   = W_sh + 8192;   // [4 grp][16 r][64 b] 4096
    float* c_sh  = red + 4096;    // [4 u][64 b]       256
    float* bh_sh = c_sh + 256;    // [16]

    const int tid = threadIdx.x;
    const int j0  = blockIdx.x * 4;

    // Preload Wh slice transposed to [k][r], r = gate*4 + u
    for (int idx = tid; idx < 8192; idx += 256) {
        const int r = idx >> 9;      // 0..15
        const int k = idx & 511;     // coalesced over k
        const int gate = r >> 2, u = r & 3;
        const float* W = gate == 0 ? Wh0 : gate == 1 ? Wh1 : gate == 2 ? Wh2 : Wh3;
        W_sh[k * 16 + r] = W[(size_t)(j0 + u) * HH + k];
    }
    if (tid < 16) {
        const int gate = tid >> 2, u = tid & 3;
        const float* bp = gate == 0 ? bh0 : gate == 1 ? bh1 : gate == 2 ? bh2 : bh3;
        bh_sh[tid] = bp[j0 + u];
    }
    c_sh[tid] = 0.f;
    for (int idx = tid; idx < 32768; idx += 256) h_sh[idx] = 0.f;   // h(-1) = 0
    __syncthreads();

    const int grp = tid >> 6;            // k-slice 0..3 (128 k each)
    const int l   = tid & 63;
    const int b0  = (l >> 2) * 4;        // batch tile
    const int r0  = (l & 3) * 4;         // gate-row tile
    const int u   = tid >> 6;            // pointwise: unit 0..3
    const int b   = tid & 63;            // pointwise: batch

    #pragma unroll 1
    for (int t = 0; t < SS; ++t) {
        if (t > 0) {
            // pull fresh h (bypass L1: written by other SMs last step)
            const float* hb = g_h[(t - 1) & 1];
            for (int idx = tid * 4; idx < 32768; idx += 1024) {
                const float4 v = __ldcg((const float4*)(hb + idx));
                *(float4*)(h_sh + idx) = v;
            }
            __syncthreads();
        }

        // GEMM partial: acc[r][b] over this group's 128-k slice
        float acc[4][4] = {};
        const float* hp = h_sh + grp * (128 * 64) + b0;
        const float* wp = W_sh + grp * (128 * 16) + r0;
        #pragma unroll 8
        for (int k = 0; k < 128; ++k) {
            const float4 hv = *(const float4*)hp;
            const float4 wv = *(const float4*)wp;
            hp += 64; wp += 16;
            acc[0][0] += wv.x * hv.x; acc[0][1] += wv.x * hv.y;
            acc[0][2] += wv.x * hv.z; acc[0][3] += wv.x * hv.w;
            acc[1][0] += wv.y * hv.x; acc[1][1] += wv.y * hv.y;
            acc[1][2] += wv.y * hv.z; acc[1][3] += wv.y * hv.w;
            acc[2][0] += wv.z * hv.x; acc[2][1] += wv.z * hv.y;
            acc[2][2] += wv.z * hv.z; acc[2][3] += wv.z * hv.w;
            acc[3][0] += wv.w * hv.x; acc[3][1] += wv.w * hv.y;
            acc[3][2] += wv.w * hv.z; acc[3][3] += wv.w * hv.w;
        }
        #pragma unroll
        for (int ri = 0; ri < 4; ++ri) {
            *(float4*)(red + grp * 1024 + (r0 + ri) * 64 + b0) =
                make_float4(acc[ri][0], acc[ri][1], acc[ri][2], acc[ri][3]);
        }
        __syncthreads();

        // Pointwise: thread -> (unit u, batch b)
        float gp[4];
        const float* xgp = g_xg + (size_t)t * GH * BB;
        #pragma unroll
        for (int gate = 0; gate < 4; ++gate) {
            const int r = gate * 4 + u;
            float s = red[r * 64 + b] + red[1024 + r * 64 + b] +
                      red[2048 + r * 64 + b] + red[3072 + r * 64 + b];
            s += xgp[(size_t)(gate * HH + j0 + u) * BB + b] + bh_sh[r];
            gp[gate] = s;
        }
        const float ig = 1.f / (1.f + expf(-gp[0]));
        const float fg = 1.f / (1.f + expf(-gp[1]));
        const float gg = tanhf(gp[2]);
        const float og = 1.f / (1.f + expf(-gp[3]));
        const float cv = fg * c_sh[u * 64 + b] + ig * gg;
        const float hv = og * tanhf(cv);
        c_sh[u * 64 + b] = cv;
        g_h[t & 1][(j0 + u) * 64 + b] = hv;
        out[((size_t)b * SS + t) * HH + j0 + u] = hv;
        if (t == SS - 1) {
            out[(size_t)BB * SS * HH + (size_t)b * HH + j0 + u] = hv;                       // h_last
            out[(size_t)BB * SS * HH + (size_t)BB * HH + (size_t)b * HH + j0 + u] = cv;     // c_last
        }

        // grid barrier (monotonic counter; reset each launch by reset_bar_k)
        __threadfence();
        __syncthreads();
        if (tid == 0) {
            atomicAdd(&g_bar, 1u);
            const unsigned tgt = (unsigned)NB * (unsigned)(t + 1);
            while (*(volatile unsigned*)&g_bar < tgt) { }
        }
        __syncthreads();
    }
}

extern "C" void kernel_launch(void* const* d_in, const int* in_sizes, int n_in,
                              void* d_out, int out_size)
{
    // Classify inputs by element count — robust to metadata ordering.
    // Input weights (H*I = 131072) appear in relative order: ii, if_, ig, io
    // Hidden weights (H*H = 262144) appear in relative order: hi, hf, hg, ho
    // Biases (H = 512) appear in relative order: ii, hi, if_, hf, ig, hg, io, ho
    const float* x = (const float*)d_in[0];
    const float* Wi[4] = {0, 0, 0, 0};   // ii, if_, ig, io
    const float* Wh[4] = {0, 0, 0, 0};   // hi, hf, hg, ho
    const float* bv[8] = {0, 0, 0, 0, 0, 0, 0, 0}; // ii,hi,if_,hf,ig,hg,io,ho
    int nwi = 0, nwh = 0, nb = 0;
    for (int i = 1; i < n_in; ++i) {
        const int sz = in_sizes[i];
        if (sz == HH * II)      { if (nwi < 4) Wi[nwi++] = (const float*)d_in[i]; }
        else if (sz == HH * HH) { if (nwh < 4) Wh[nwh++] = (const float*)d_in[i]; }
        else if (sz == HH)      { if (nb  < 8) bv[nb++]  = (const float*)d_in[i]; }
    }
    const float* bii = bv[0];
    const float* bhi = bv[1];
    const float* bif = bv[2];
    const float* bhf = bv[3];
    const float* big = bv[4];
    const float* bhg = bv[5];
    const float* bio = bv[6];
    const float* bho = bv[7];
    float* out = (float*)d_out;

    cudaFuncSetAttribute(gemm_in,  cudaFuncAttributeMaxDynamicSharedMemorySize, 65536);
    cudaFuncSetAttribute(lstm_rec, cudaFuncAttributeMaxDynamicSharedMemorySize, 181312);

    dim3 g1(32, SS);
    gemm_in<<<g1, 256, 65536>>>(x, Wi[0], Wi[1], Wi[2], Wi[3], bii, bif, big, bio);
    reset_bar_k<<<1, 1>>>();
    lstm_rec<<<NB, 256, 181312>>>(Wh[0], Wh[1], Wh[2], Wh[3], bhi, bhf, bhg, bho, out);
}

// round 5
// speedup vs baseline: 1.3472x; 1.3472x over previous
#include <cuda_runtime.h>
#include <math.h>

#define BB 64
#define SS 1024
#define II 256
#define HH 512
#define GH 2048   // 4*H
#define NB 128    // persistent blocks for recurrence
#define PAD 134   // smem row stride (floats): ≡2 mod 4 (STS.64-aligned), bank stride 6 -> conflict-free scalar reads

// Scratch (static __device__ allowed; no runtime allocs).
__device__ float   g_xg[134217728];   // [S][2048][64]  x-side gate preacts (+bi), 512MB
__device__ float   g_h[2][HH * BB];   // [j][b] double-buffered hidden state
__device__ unsigned g_bar;            // grid barrier counter

__global__ void reset_bar_k() { g_bar = 0u; }

// ---------------------------------------------------------------------------
// Kernel 1: x_gates[t][g][b] = sum_i x[b][t][i] * Wi[g][i] + bi[g]
// grid (32 gate-tiles of 64, 1024 timesteps), 256 threads.
// Natural-layout smem tiles (no transpose); scalar conflict-free reads.
// Thread owns g rows {g_lo, g_lo+16, g_lo+32, g_lo+48} x b cols {b0..b0+3}.
// ---------------------------------------------------------------------------
__global__ void __launch_bounds__(256) gemm_in(
    const float* __restrict__ x,
    const float* __restrict__ W0, const float* __restrict__ W1,
    const float* __restrict__ W2, const float* __restrict__ W3,
    const float* __restrict__ bi0, const float* __restrict__ bi1,
    const float* __restrict__ bi2, const float* __restrict__ bi3)
{
    extern __shared__ float sm[];
    float* xs = sm;             // [64 b][PAD] cols 0..127 = i
    float* ws = sm + 64 * PAD;  // [64 g][PAD] cols 0..127 = i

    const int t   = blockIdx.y;
    const int gt  = blockIdx.x;          // 0..31 (64 gate rows each)
    const int tid = threadIdx.x;
    const int gate = gt >> 3;            // 8 tiles per gate (512/64)
    const float* W  = gate == 0 ? W0 : gate == 1 ? W1 : gate == 2 ? W2 : W3;
    const float* bi = gate == 0 ? bi0 : gate == 1 ? bi1 : gate == 2 ? bi2 : bi3;
    const int u0 = (gt & 7) * 64;        // unit offset inside this gate

    const int g_lo = tid & 15;           // thread's g rows: g_lo + 16*gi
    const int b0   = (tid >> 4) * 4;     // thread's b cols: b0..b0+3
    float acc[4][4] = {};

    for (int kc = 0; kc < 2; ++kc) {
        const int koff = kc * 128;
        // fill xs[b][0..127]: coalesced float4 loads, aligned STS.64 stores
        for (int idx = tid; idx < 2048; idx += 256) {
            const int row = idx >> 5, q = idx & 31;
            const float4 v = *(const float4*)(x + ((size_t)row * SS + t) * II + koff + q * 4);
            float* p = xs + row * PAD + q * 4;
            *(float2*)(p)     = make_float2(v.x, v.y);
            *(float2*)(p + 2) = make_float2(v.z, v.w);
        }
        // fill ws[g][0..127]
        for (int idx = tid; idx < 2048; idx += 256) {
            const int row = idx >> 5, q = idx & 31;
            const float4 v = *(const float4*)(W + (size_t)(u0 + row) * II + koff + q * 4);
            float* p = ws + row * PAD + q * 4;
            *(float2*)(p)     = make_float2(v.x, v.y);
            *(float2*)(p + 2) = make_float2(v.z, v.w);
        }
        __syncthreads();

        const float* xr0 = xs + (b0 + 0) * PAD;
        const float* xr1 = xs + (b0 + 1) * PAD;
        const float* xr2 = xs + (b0 + 2) * PAD;
        const float* xr3 = xs + (b0 + 3) * PAD;
        const float* wr0 = ws + (g_lo +  0) * PAD;
        const float* wr1 = ws + (g_lo + 16) * PAD;
        const float* wr2 = ws + (g_lo + 32) * PAD;
        const float* wr3 = ws + (g_lo + 48) * PAD;
        #pragma unroll 4
        for (int i = 0; i < 128; ++i) {
            const float x0 = xr0[i], x1 = xr1[i], x2 = xr2[i], x3 = xr3[i];
            const float w0 = wr0[i], w1 = wr1[i], w2 = wr2[i], w3 = wr3[i];
            acc[0][0] += w0 * x0; acc[0][1] += w0 * x1; acc[0][2] += w0 * x2; acc[0][3] += w0 * x3;
            acc[1][0] += w1 * x0; acc[1][1] += w1 * x1; acc[1][2] += w1 * x2; acc[1][3] += w1 * x3;
            acc[2][0] += w2 * x0; acc[2][1] += w2 * x1; acc[2][2] += w2 * x2; acc[2][3] += w2 * x3;
            acc[3][0] += w3 * x0; acc[3][1] += w3 * x1; acc[3][2] += w3 * x2; acc[3][3] += w3 * x3;
        }
        __syncthreads();
    }

    // output: row r = g_lo + 16*gi within tile; float4 along b
    #pragma unroll
    for (int gi = 0; gi < 4; ++gi) {
        const int r = g_lo + 16 * gi;
        const float bvv = bi[u0 + r];
        const size_t obase = (size_t)t * GH * BB + (size_t)(gate * HH + u0 + r) * BB + b0;
        const float4 o = make_float4(acc[gi][0] + bvv, acc[gi][1] + bvv,
                                     acc[gi][2] + bvv, acc[gi][3] + bvv);
        *(float4*)(g_xg + obase) = o;
    }
}

// ---------------------------------------------------------------------------
// Kernel 2: persistent recurrence. 128 blocks x 256 threads, 1 block/SM.
// Block owns hidden units [4*bid, 4*bid+4). h exchanged via global double
// buffer + atomic grid barrier each step. xg prefetched into registers.
// ---------------------------------------------------------------------------
__global__ void __launch_bounds__(256, 1) lstm_rec(
    const float* __restrict__ Wh0, const float* __restrict__ Wh1,
    const float* __restrict__ Wh2, const float* __restrict__ Wh3,
    const float* __restrict__ bh0, const float* __restrict__ bh1,
    const float* __restrict__ bh2, const float* __restrict__ bh3,
    float* __restrict__ out)
{
    extern __shared__ float sm[];
    float* h_sh  = sm;            // [512 k][64 b]   32768
    float* W_sh  = sm + 32768;    // [512 k][16 r]    8192
    float* red   = W_sh + 8192;   // [4 grp][16 r][64 b] 4096
    float* c_sh  = red + 4096;    // [4 u][64 b]       256
    float* bh_sh = c_sh + 256;    // [16]

    const int tid = threadIdx.x;
    const int j0  = blockIdx.x * 4;

    // Preload Wh slice transposed to [k][r], r = gate*4 + u
    for (int idx = tid; idx < 8192; idx += 256) {
        const int r = idx >> 9;      // 0..15
        const int k = idx & 511;     // coalesced over k
        const int gate = r >> 2, u = r & 3;
        const float* W = gate == 0 ? Wh0 : gate == 1 ? Wh1 : gate == 2 ? Wh2 : Wh3;
        W_sh[k * 16 + r] = W[(size_t)(j0 + u) * HH + k];
    }
    if (tid < 16) {
        const int gate = tid >> 2, u = tid & 3;
        const float* bp = gate == 0 ? bh0 : gate == 1 ? bh1 : gate == 2 ? bh2 : bh3;
        bh_sh[tid] = bp[j0 + u];
    }
    c_sh[tid] = 0.f;
    for (int idx = tid; idx < 32768; idx += 256) h_sh[idx] = 0.f;   // h(-1) = 0
    __syncthreads();

    const int grp = tid >> 6;            // k-slice 0..3 (128 k each)
    const int l   = tid & 63;
    const int b0  = (l >> 2) * 4;        // batch tile
    const int r0  = (l & 3) * 4;         // gate-row tile
    const int u   = tid >> 6;            // pointwise: unit 0..3
    const int b   = tid & 63;            // pointwise: batch

    #pragma unroll 1
    for (int t = 0; t < SS; ++t) {
        // Prefetch this step's x-side gate preacts (independent of h).
        float xg_r[4];
        {
            const float* xgp = g_xg + (size_t)t * GH * BB;
            #pragma unroll
            for (int gate = 0; gate < 4; ++gate)
                xg_r[gate] = __ldg(xgp + (size_t)(gate * HH + j0 + u) * BB + b);
        }

        if (t > 0) {
            // pull fresh h (bypass L1: written by other SMs last step)
            const float* hb = g_h[(t - 1) & 1];
            for (int idx = tid * 4; idx < 32768; idx += 1024) {
                const float4 v = __ldcg((const float4*)(hb + idx));
                *(float4*)(h_sh + idx) = v;
            }
            __syncthreads();
        }

        // GEMM partial: acc[r][b] over this group's 128-k slice
        float acc[4][4] = {};
        const float* hp = h_sh + grp * (128 * 64) + b0;
        const float* wp = W_sh + grp * (128 * 16) + r0;
        #pragma unroll 8
        for (int k = 0; k < 128; ++k) {
            const float4 hv = *(const float4*)hp;
            const float4 wv = *(const float4*)wp;
            hp += 64; wp += 16;
            acc[0][0] += wv.x * hv.x; acc[0][1] += wv.x * hv.y;
            acc[0][2] += wv.x * hv.z; acc[0][3] += wv.x * hv.w;
            acc[1][0] += wv.y * hv.x; acc[1][1] += wv.y * hv.y;
            acc[1][2] += wv.y * hv.z; acc[1][3] += wv.y * hv.w;
            acc[2][0] += wv.z * hv.x; acc[2][1] += wv.z * hv.y;
            acc[2][2] += wv.z * hv.z; acc[2][3] += wv.z * hv.w;
            acc[3][0] += wv.w * hv.x; acc[3][1] += wv.w * hv.y;
            acc[3][2] += wv.w * hv.z; acc[3][3] += wv.w * hv.w;
        }
        #pragma unroll
        for (int ri = 0; ri < 4; ++ri) {
            *(float4*)(red + grp * 1024 + (r0 + ri) * 64 + b0) =
                make_float4(acc[ri][0], acc[ri][1], acc[ri][2], acc[ri][3]);
        }
        __syncthreads();

        // Pointwise: thread -> (unit u, batch b)
        float gp[4];
        #pragma unroll
        for (int gate = 0; gate < 4; ++gate) {
            const int r = gate * 4 + u;
            float s = red[r * 64 + b] + red[1024 + r * 64 + b] +
                      red[2048 + r * 64 + b] + red[3072 + r * 64 + b];
            s += xg_r[gate] + bh_sh[r];
            gp[gate] = s;
        }
        const float ig = 1.f / (1.f + expf(-gp[0]));
        const float fg = 1.f / (1.f + expf(-gp[1]));
        const float gg = tanhf(gp[2]);
        const float og = 1.f / (1.f + expf(-gp[3]));
        const float cv = fg * c_sh[u * 64 + b] + ig * gg;
        const float hv = og * tanhf(cv);
        c_sh[u * 64 + b] = cv;
        g_h[t & 1][(j0 + u) * 64 + b] = hv;
        out[((size_t)b * SS + t) * HH + j0 + u] = hv;
        if (t == SS - 1) {
            out[(size_t)BB * SS * HH + (size_t)b * HH + j0 + u] = hv;                       // h_last
            out[(size_t)BB * SS * HH + (size_t)BB * HH + (size_t)b * HH + j0 + u] = cv;     // c_last
        }

        // grid barrier (monotonic counter; reset each launch by reset_bar_k)
        __threadfence();
        __syncthreads();
        if (tid == 0) {
            atomicAdd(&g_bar, 1u);
            const unsigned tgt = (unsigned)NB * (unsigned)(t + 1);
            while (*(volatile unsigned*)&g_bar < tgt) { }
        }
        __syncthreads();
    }
}

extern "C" void kernel_launch(void* const* d_in, const int* in_sizes, int n_in,
                              void* d_out, int out_size)
{
    // Classify inputs by element count — robust to metadata ordering.
    const float* x = (const float*)d_in[0];
    const float* Wi[4] = {0, 0, 0, 0};   // ii, if_, ig, io
    const float* Wh[4] = {0, 0, 0, 0};   // hi, hf, hg, ho
    const float* bv[8] = {0, 0, 0, 0, 0, 0, 0, 0}; // ii,hi,if_,hf,ig,hg,io,ho
    int nwi = 0, nwh = 0, nb = 0;
    for (int i = 1; i < n_in; ++i) {
        const int sz = in_sizes[i];
        if (sz == HH * II)      { if (nwi < 4) Wi[nwi++] = (const float*)d_in[i]; }
        else if (sz == HH * HH) { if (nwh < 4) Wh[nwh++] = (const float*)d_in[i]; }
        else if (sz == HH)      { if (nb  < 8) bv[nb++]  = (const float*)d_in[i]; }
    }
    const float* bii = bv[0];
    const float* bhi = bv[1];
    const float* bif = bv[2];
    const float* bhf = bv[3];
    const float* big = bv[4];
    const float* bhg = bv[5];
    const float* bio = bv[6];
    const float* bho = bv[7];
    float* out = (float*)d_out;

    const int gemm_smem = 2 * 64 * PAD * 4;   // 68,608 B
    cudaFuncSetAttribute(gemm_in,  cudaFuncAttributeMaxDynamicSharedMemorySize, gemm_smem);
    cudaFuncSetAttribute(lstm_rec, cudaFuncAttributeMaxDynamicSharedMemorySize, 181312);

    dim3 g1(32, SS);
    gemm_in<<<g1, 256, gemm_smem>>>(x, Wi[0], Wi[1], Wi[2], Wi[3], bii, bif, big, bio);
    reset_bar_k<<<1, 1>>>();
    lstm_rec<<<NB, 256, 181312>>>(Wh[0], Wh[1], Wh[2], Wh[3], bhi, bhf, bhg, bho, out);
}

// round 6
// speedup vs baseline: 1.4039x; 1.0421x over previous
#include <cuda_runtime.h>
#include <math.h>
#include <stdint.h>

#define BB 64
#define SS 1024
#define II 256
#define HH 512
#define GH 2048   // 4*H
#define NB 128    // persistent blocks for recurrence
#define AST 66    // smem stride for mma tiles (floats): even, ≡2 mod 4, 2-way max conflicts

// Scratch (static __device__ allowed; no runtime allocs).
__device__ float   g_xg[134217728];   // [S][2048][64]  x-side gate preacts (+bi), 512MB
__device__ float   g_h[2][HH * BB];   // [j][b] double-buffered hidden state
__device__ unsigned g_bar;            // grid barrier counter

__global__ void reset_bar_k() { g_bar = 0u; }

// Dekker-ish split: v = hi + lo, hi = tf32-rounded (11-bit mantissa), lo exact in fp32.
__device__ __forceinline__ void split_tf32(float v, float& hi, float& lo) {
    uint32_t u;
    asm("cvt.rna.tf32.f32 %0, %1;" : "=r"(u) : "f"(v));
    hi = __uint_as_float(u);
    lo = v - hi;
}

__device__ __forceinline__ void mma_tf32(float c[4],
                                         uint32_t a0, uint32_t a1, uint32_t a2, uint32_t a3,
                                         uint32_t b0, uint32_t b1) {
    asm volatile(
        "mma.sync.aligned.m16n8k8.row.col.f32.tf32.tf32.f32 "
        "{%0,%1,%2,%3}, {%4,%5,%6,%7}, {%8,%9}, {%0,%1,%2,%3};\n"
        : "+f"(c[0]), "+f"(c[1]), "+f"(c[2]), "+f"(c[3])
        : "r"(a0), "r"(a1), "r"(a2), "r"(a3), "r"(b0), "r"(b1));
}

// ---------------------------------------------------------------------------
// Kernel 1 (tensor cores): x_gates[t][G][b] = sum_i x[b][t][i]*Wi[G][i] + bi
// Block tile: 128 g-rows x 64 b, K=256 in 4 chunks of 64. TF32 x3 (hi/lo).
// 8 warps as (4 warpRows of 32g) x (2 warpCols of 32b); warp: 2 m-tiles x 4 n-tiles.
// grid (16 g-tiles, 1024 t).
// ---------------------------------------------------------------------------
__global__ void __launch_bounds__(256, 2) gemm_in_mma(
    const float* __restrict__ x,
    const float* __restrict__ W0, const float* __restrict__ W1,
    const float* __restrict__ W2, const float* __restrict__ W3,
    const float* __restrict__ bi0, const float* __restrict__ bi1,
    const float* __restrict__ bi2, const float* __restrict__ bi3)
{
    extern __shared__ float sm[];
    float* A_hi = sm;                     // [128][AST]
    float* A_lo = A_hi + 128 * AST;
    float* B_hi = A_lo + 128 * AST;       // [64][AST]
    float* B_lo = B_hi + 64 * AST;        // total 25344 floats = 101376 B

    const int t    = blockIdx.y;
    const int gt   = blockIdx.x;         // 0..15
    const int gate = gt >> 2;
    const int u0   = (gt & 3) * 128;     // row offset within gate
    const float* W  = gate == 0 ? W0 : gate == 1 ? W1 : gate == 2 ? W2 : W3;
    const float* bi = gate == 0 ? bi0 : gate == 1 ? bi1 : gate == 2 ? bi2 : bi3;

    const int tid  = threadIdx.x;
    const int wid  = tid >> 5;
    const int lane = tid & 31;
    const int wr   = wid >> 1;           // 0..3 (g)
    const int wc   = wid & 1;            // 0..1 (b)
    const int l4   = lane >> 2;          // 0..7
    const int lq   = lane & 3;           // 0..3

    float c[2][4][4];
    #pragma unroll
    for (int mt = 0; mt < 2; ++mt)
        #pragma unroll
        for (int nt = 0; nt < 4; ++nt)
            #pragma unroll
            for (int i = 0; i < 4; ++i) c[mt][nt][i] = 0.f;

    for (int kc = 0; kc < 4; ++kc) {
        const int koff = kc * 64;
        // Fill A (W rows u0..u0+127, k chunk), split hi/lo
        for (int idx = tid; idx < 2048; idx += 256) {
            const int row = idx >> 4, q = idx & 15;
            const float4 v = *(const float4*)(W + (size_t)(u0 + row) * II + koff + q * 4);
            float h0, l0, h1, l1, h2, l2, h3, l3;
            split_tf32(v.x, h0, l0); split_tf32(v.y, h1, l1);
            split_tf32(v.z, h2, l2); split_tf32(v.w, h3, l3);
            float* ph = A_hi + row * AST + q * 4;
            float* pl = A_lo + row * AST + q * 4;
            *(float2*)(ph)     = make_float2(h0, h1);
            *(float2*)(ph + 2) = make_float2(h2, h3);
            *(float2*)(pl)     = make_float2(l0, l1);
            *(float2*)(pl + 2) = make_float2(l2, l3);
        }
        // Fill B (x rows b=0..63, k chunk), split hi/lo
        for (int idx = tid; idx < 1024; idx += 256) {
            const int row = idx >> 4, q = idx & 15;
            const float4 v = *(const float4*)(x + ((size_t)row * SS + t) * II + koff + q * 4);
            float h0, l0, h1, l1, h2, l2, h3, l3;
            split_tf32(v.x, h0, l0); split_tf32(v.y, h1, l1);
            split_tf32(v.z, h2, l2); split_tf32(v.w, h3, l3);
            float* ph = B_hi + row * AST + q * 4;
            float* pl = B_lo + row * AST + q * 4;
            *(float2*)(ph)     = make_float2(h0, h1);
            *(float2*)(ph + 2) = make_float2(h2, h3);
            *(float2*)(pl)     = make_float2(l0, l1);
            *(float2*)(pl + 2) = make_float2(l2, l3);
        }
        __syncthreads();

        #pragma unroll 2
        for (int k8 = 0; k8 < 8; ++k8) {
            const int kk = k8 * 8;
            // A fragments (m16n8k8 row-major):
            // a0:(g,k) a1:(g+8,k) a2:(g,k+4) a3:(g+8,k+4); g=gbase+l4, k=kk+lq
            uint32_t ah[2][4], al[2][4];
            #pragma unroll
            for (int mt = 0; mt < 2; ++mt) {
                const int g = wr * 32 + mt * 16 + l4;
                const int base = g * AST + kk + lq;
                ah[mt][0] = __float_as_uint(A_hi[base]);
                ah[mt][1] = __float_as_uint(A_hi[base + 8 * AST]);
                ah[mt][2] = __float_as_uint(A_hi[base + 4]);
                ah[mt][3] = __float_as_uint(A_hi[base + 8 * AST + 4]);
                al[mt][0] = __float_as_uint(A_lo[base]);
                al[mt][1] = __float_as_uint(A_lo[base + 8 * AST]);
                al[mt][2] = __float_as_uint(A_lo[base + 4]);
                al[mt][3] = __float_as_uint(A_lo[base + 8 * AST + 4]);
            }
            #pragma unroll
            for (int nt = 0; nt < 4; ++nt) {
                // B fragments (col-major 8k x 8n): b0:(n=l4,k=kk+lq) b1:(k+4)
                const int b = wc * 32 + nt * 8 + l4;
                const int bb = b * AST + kk + lq;
                const uint32_t bh0 = __float_as_uint(B_hi[bb]);
                const uint32_t bh1 = __float_as_uint(B_hi[bb + 4]);
                const uint32_t bl0 = __float_as_uint(B_lo[bb]);
                const uint32_t bl1 = __float_as_uint(B_lo[bb + 4]);
                #pragma unroll
                for (int mt = 0; mt < 2; ++mt) {
                    mma_tf32(c[mt][nt], ah[mt][0], ah[mt][1], ah[mt][2], ah[mt][3], bh0, bh1);
                    mma_tf32(c[mt][nt], ah[mt][0], ah[mt][1], ah[mt][2], ah[mt][3], bl0, bl1);
                    mma_tf32(c[mt][nt], al[mt][0], al[mt][1], al[mt][2], al[mt][3], bh0, bh1);
                }
            }
        }
        __syncthreads();
    }

    // Epilogue: c frag -> g_xg[t][gate*512 + r][b], add input bias.
    #pragma unroll
    for (int mt = 0; mt < 2; ++mt) {
        const int r_lo = u0 + wr * 32 + mt * 16 + l4;   // within gate, rows r_lo, r_lo+8
        const float bv0 = __ldg(bi + r_lo);
        const float bv1 = __ldg(bi + r_lo + 8);
        const size_t G0 = (size_t)gate * HH + r_lo;
        #pragma unroll
        for (int nt = 0; nt < 4; ++nt) {
            const int bcol = wc * 32 + nt * 8 + lq * 2;
            float* p0 = g_xg + ((size_t)t * GH + G0) * BB + bcol;
            float* p1 = g_xg + ((size_t)t * GH + G0 + 8) * BB + bcol;
            *(float2*)p0 = make_float2(c[mt][nt][0] + bv0, c[mt][nt][1] + bv0);
            *(float2*)p1 = make_float2(c[mt][nt][2] + bv1, c[mt][nt][3] + bv1);
        }
    }
}

// ---------------------------------------------------------------------------
// Kernel 2: persistent recurrence (unchanged from round-5 passing version).
// ---------------------------------------------------------------------------
__global__ void __launch_bounds__(256, 1) lstm_rec(
    const float* __restrict__ Wh0, const float* __restrict__ Wh1,
    const float* __restrict__ Wh2, const float* __restrict__ Wh3,
    const float* __restrict__ bh0, const float* __restrict__ bh1,
    const float* __restrict__ bh2, const float* __restrict__ bh3,
    float* __restrict__ out)
{
    extern __shared__ float sm[];
    float* h_sh  = sm;            // [512 k][64 b]   32768
    float* W_sh  = sm + 32768;    // [512 k][16 r]    8192
    float* red   = W_sh + 8192;   // [4 grp][16 r][64 b] 4096
    float* c_sh  = red + 4096;    // [4 u][64 b]       256
    float* bh_sh = c_sh + 256;    // [16]

    const int tid = threadIdx.x;
    const int j0  = blockIdx.x * 4;

    for (int idx = tid; idx < 8192; idx += 256) {
        const int r = idx >> 9;
        const int k = idx & 511;
        const int gate = r >> 2, u = r & 3;
        const float* W = gate == 0 ? Wh0 : gate == 1 ? Wh1 : gate == 2 ? Wh2 : Wh3;
        W_sh[k * 16 + r] = W[(size_t)(j0 + u) * HH + k];
    }
    if (tid < 16) {
        const int gate = tid >> 2, u = tid & 3;
        const float* bp = gate == 0 ? bh0 : gate == 1 ? bh1 : gate == 2 ? bh2 : bh3;
        bh_sh[tid] = bp[j0 + u];
    }
    c_sh[tid] = 0.f;
    for (int idx = tid; idx < 32768; idx += 256) h_sh[idx] = 0.f;
    __syncthreads();

    const int grp = tid >> 6;
    const int l   = tid & 63;
    const int b0  = (l >> 2) * 4;
    const int r0  = (l & 3) * 4;
    const int u   = tid >> 6;
    const int b   = tid & 63;

    #pragma unroll 1
    for (int t = 0; t < SS; ++t) {
        float xg_r[4];
        {
            const float* xgp = g_xg + (size_t)t * GH * BB;
            #pragma unroll
            for (int gate = 0; gate < 4; ++gate)
                xg_r[gate] = __ldg(xgp + (size_t)(gate * HH + j0 + u) * BB + b);
        }

        if (t > 0) {
            const float* hb = g_h[(t - 1) & 1];
            for (int idx = tid * 4; idx < 32768; idx += 1024) {
                const float4 v = __ldcg((const float4*)(hb + idx));
                *(float4*)(h_sh + idx) = v;
            }
            __syncthreads();
        }

        float acc[4][4] = {};
        const float* hp = h_sh + grp * (128 * 64) + b0;
        const float* wp = W_sh + grp * (128 * 16) + r0;
        #pragma unroll 8
        for (int k = 0; k < 128; ++k) {
            const float4 hv = *(const float4*)hp;
            const float4 wv = *(const float4*)wp;
            hp += 64; wp += 16;
            acc[0][0] += wv.x * hv.x; acc[0][1] += wv.x * hv.y;
            acc[0][2] += wv.x * hv.z; acc[0][3] += wv.x * hv.w;
            acc[1][0] += wv.y * hv.x; acc[1][1] += wv.y * hv.y;
            acc[1][2] += wv.y * hv.z; acc[1][3] += wv.y * hv.w;
            acc[2][0] += wv.z * hv.x; acc[2][1] += wv.z * hv.y;
            acc[2][2] += wv.z * hv.z; acc[2][3] += wv.z * hv.w;
            acc[3][0] += wv.w * hv.x; acc[3][1] += wv.w * hv.y;
            acc[3][2] += wv.w * hv.z; acc[3][3] += wv.w * hv.w;
        }
        #pragma unroll
        for (int ri = 0; ri < 4; ++ri) {
            *(float4*)(red + grp * 1024 + (r0 + ri) * 64 + b0) =
                make_float4(acc[ri][0], acc[ri][1], acc[ri][2], acc[ri][3]);
        }
        __syncthreads();

        float gp[4];
        #pragma unroll
        for (int gate = 0; gate < 4; ++gate) {
            const int r = gate * 4 + u;
            float s = red[r * 64 + b] + red[1024 + r * 64 + b] +
                      red[2048 + r * 64 + b] + red[3072 + r * 64 + b];
            s += xg_r[gate] + bh_sh[r];
            gp[gate] = s;
        }
        const float ig = 1.f / (1.f + expf(-gp[0]));
        const float fg = 1.f / (1.f + expf(-gp[1]));
        const float gg = tanhf(gp[2]);
        const float og = 1.f / (1.f + expf(-gp[3]));
        const float cv = fg * c_sh[u * 64 + b] + ig * gg;
        const float hv = og * tanhf(cv);
        c_sh[u * 64 + b] = cv;
        g_h[t & 1][(j0 + u) * 64 + b] = hv;
        out[((size_t)b * SS + t) * HH + j0 + u] = hv;
        if (t == SS - 1) {
            out[(size_t)BB * SS * HH + (size_t)b * HH + j0 + u] = hv;
            out[(size_t)BB * SS * HH + (size_t)BB * HH + (size_t)b * HH + j0 + u] = cv;
        }

        __threadfence();
        __syncthreads();
        if (tid == 0) {
            atomicAdd(&g_bar, 1u);
            const unsigned tgt = (unsigned)NB * (unsigned)(t + 1);
            while (*(volatile unsigned*)&g_bar < tgt) { }
        }
        __syncthreads();
    }
}

extern "C" void kernel_launch(void* const* d_in, const int* in_sizes, int n_in,
                              void* d_out, int out_size)
{
    // Classify inputs by element count — robust to metadata ordering.
    const float* x = (const float*)d_in[0];
    const float* Wi[4] = {0, 0, 0, 0};   // ii, if_, ig, io
    const float* Wh[4] = {0, 0, 0, 0};   // hi, hf, hg, ho
    const float* bv[8] = {0, 0, 0, 0, 0, 0, 0, 0}; // ii,hi,if_,hf,ig,hg,io,ho
    int nwi = 0, nwh = 0, nb = 0;
    for (int i = 1; i < n_in; ++i) {
        const int sz = in_sizes[i];
        if (sz == HH * II)      { if (nwi < 4) Wi[nwi++] = (const float*)d_in[i]; }
        else if (sz == HH * HH) { if (nwh < 4) Wh[nwh++] = (const float*)d_in[i]; }
        else if (sz == HH)      { if (nb  < 8) bv[nb++]  = (const float*)d_in[i]; }
    }
    const float* bii = bv[0];
    const float* bhi = bv[1];
    const float* bif = bv[2];
    const float* bhf = bv[3];
    const float* big = bv[4];
    const float* bhg = bv[5];
    const float* bio = bv[6];
    const float* bho = bv[7];
    float* out = (float*)d_out;

    const int gemm_smem = (2 * 128 * AST + 2 * 64 * AST) * 4;   // 101,376 B
    cudaFuncSetAttribute(gemm_in_mma, cudaFuncAttributeMaxDynamicSharedMemorySize, gemm_smem);
    cudaFuncSetAttribute(lstm_rec,    cudaFuncAttributeMaxDynamicSharedMemorySize, 181312);

    dim3 g1(16, SS);
    gemm_in_mma<<<g1, 256, gemm_smem>>>(x, Wi[0], Wi[1], Wi[2], Wi[3], bii, bif, big, bio);
    reset_bar_k<<<1, 1>>>();
    lstm_rec<<<NB, 256, 181312>>>(Wh[0], Wh[1], Wh[2], Wh[3], bhi, bhf, bhg, bho, out);
}

// round 8
// speedup vs baseline: 1.6941x; 1.2067x over previous
#include <cuda_runtime.h>
#include <cuda_bf16.h>
#include <math.h>
#include <stdint.h>

#define BB 64
#define SS 1024
#define II 256
#define HH 512
#define GH 2048   // 4*H
#define NB 128    // persistent blocks for recurrence
#define AST 66    // gemm smem stride (floats)
#define HS 520    // recurrence smem row stride in bf16 (260 words ≡ 4 mod 32)

// Scratch (static __device__ allowed; no runtime allocs).
__device__ float         g_xg[134217728];    // [S][2048][64] x-side gate preacts (+bi)
__device__ __nv_bfloat16 g_hb[2][2][32768];  // [buf][hi/lo][b*512 + j] hidden state planes
__device__ unsigned      g_bar;              // grid barrier counter

__global__ void reset_bar_k() { g_bar = 0u; }

// tf32 split for gemm_in
__device__ __forceinline__ void split_tf32(float v, float& hi, float& lo) {
    uint32_t u;
    asm("cvt.rna.tf32.f32 %0, %1;" : "=r"(u) : "f"(v));
    hi = __uint_as_float(u);
    lo = v - hi;
}

__device__ __forceinline__ void mma_tf32(float c[4],
                                         uint32_t a0, uint32_t a1, uint32_t a2, uint32_t a3,
                                         uint32_t b0, uint32_t b1) {
    asm volatile(
        "mma.sync.aligned.m16n8k8.row.col.f32.tf32.tf32.f32 "
        "{%0,%1,%2,%3}, {%4,%5,%6,%7}, {%8,%9}, {%0,%1,%2,%3};\n"
        : "+f"(c[0]), "+f"(c[1]), "+f"(c[2]), "+f"(c[3])
        : "r"(a0), "r"(a1), "r"(a2), "r"(a3), "r"(b0), "r"(b1));
}

__device__ __forceinline__ void mma_bf16(float c[4],
                                         uint32_t a0, uint32_t a1, uint32_t a2, uint32_t a3,
                                         uint32_t b0, uint32_t b1) {
    asm volatile(
        "mma.sync.aligned.m16n8k16.row.col.f32.bf16.bf16.f32 "
        "{%0,%1,%2,%3}, {%4,%5,%6,%7}, {%8,%9}, {%0,%1,%2,%3};\n"
        : "+f"(c[0]), "+f"(c[1]), "+f"(c[2]), "+f"(c[3])
        : "r"(a0), "r"(a1), "r"(a2), "r"(a3), "r"(b0), "r"(b1));
}

// ---------------------------------------------------------------------------
// Kernel 1 (unchanged from round-6 passing): TF32 x3 input GEMM.
// ---------------------------------------------------------------------------
__global__ void __launch_bounds__(256, 2) gemm_in_mma(
    const float* __restrict__ x,
    const float* __restrict__ W0, const float* __restrict__ W1,
    const float* __restrict__ W2, const float* __restrict__ W3,
    const float* __restrict__ bi0, const float* __restrict__ bi1,
    const float* __restrict__ bi2, const float* __restrict__ bi3)
{
    extern __shared__ float sm[];
    float* A_hi = sm;
    float* A_lo = A_hi + 128 * AST;
    float* B_hi = A_lo + 128 * AST;
    float* B_lo = B_hi + 64 * AST;

    const int t    = blockIdx.y;
    const int gt   = blockIdx.x;
    const int gate = gt >> 2;
    const int u0   = (gt & 3) * 128;
    const float* W  = gate == 0 ? W0 : gate == 1 ? W1 : gate == 2 ? W2 : W3;
    const float* bi = gate == 0 ? bi0 : gate == 1 ? bi1 : gate == 2 ? bi2 : bi3;

    const int tid  = threadIdx.x;
    const int wid  = tid >> 5;
    const int lane = tid & 31;
    const int wr   = wid >> 1;
    const int wc   = wid & 1;
    const int l4   = lane >> 2;
    const int lq   = lane & 3;

    float c[2][4][4];
    #pragma unroll
    for (int mt = 0; mt < 2; ++mt)
        #pragma unroll
        for (int nt = 0; nt < 4; ++nt)
            #pragma unroll
            for (int i = 0; i < 4; ++i) c[mt][nt][i] = 0.f;

    for (int kc = 0; kc < 4; ++kc) {
        const int koff = kc * 64;
        for (int idx = tid; idx < 2048; idx += 256) {
            const int row = idx >> 4, q = idx & 15;
            const float4 v = *(const float4*)(W + (size_t)(u0 + row) * II + koff + q * 4);
            float h0, l0, h1, l1, h2, l2, h3, l3;
            split_tf32(v.x, h0, l0); split_tf32(v.y, h1, l1);
            split_tf32(v.z, h2, l2); split_tf32(v.w, h3, l3);
            float* ph = A_hi + row * AST + q * 4;
            float* pl = A_lo + row * AST + q * 4;
            *(float2*)(ph)     = make_float2(h0, h1);
            *(float2*)(ph + 2) = make_float2(h2, h3);
            *(float2*)(pl)     = make_float2(l0, l1);
            *(float2*)(pl + 2) = make_float2(l2, l3);
        }
        for (int idx = tid; idx < 1024; idx += 256) {
            const int row = idx >> 4, q = idx & 15;
            const float4 v = *(const float4*)(x + ((size_t)row * SS + t) * II + koff + q * 4);
            float h0, l0, h1, l1, h2, l2, h3, l3;
            split_tf32(v.x, h0, l0); split_tf32(v.y, h1, l1);
            split_tf32(v.z, h2, l2); split_tf32(v.w, h3, l3);
            float* ph = B_hi + row * AST + q * 4;
            float* pl = B_lo + row * AST + q * 4;
            *(float2*)(ph)     = make_float2(h0, h1);
            *(float2*)(ph + 2) = make_float2(h2, h3);
            *(float2*)(pl)     = make_float2(l0, l1);
            *(float2*)(pl + 2) = make_float2(l2, l3);
        }
        __syncthreads();

        #pragma unroll 2
        for (int k8 = 0; k8 < 8; ++k8) {
            const int kk = k8 * 8;
            uint32_t ah[2][4], al[2][4];
            #pragma unroll
            for (int mt = 0; mt < 2; ++mt) {
                const int g = wr * 32 + mt * 16 + l4;
                const int base = g * AST + kk + lq;
                ah[mt][0] = __float_as_uint(A_hi[base]);
                ah[mt][1] = __float_as_uint(A_hi[base + 8 * AST]);
                ah[mt][2] = __float_as_uint(A_hi[base + 4]);
                ah[mt][3] = __float_as_uint(A_hi[base + 8 * AST + 4]);
                al[mt][0] = __float_as_uint(A_lo[base]);
                al[mt][1] = __float_as_uint(A_lo[base + 8 * AST]);
                al[mt][2] = __float_as_uint(A_lo[base + 4]);
                al[mt][3] = __float_as_uint(A_lo[base + 8 * AST + 4]);
            }
            #pragma unroll
            for (int nt = 0; nt < 4; ++nt) {
                const int b = wc * 32 + nt * 8 + l4;
                const int bb = b * AST + kk + lq;
                const uint32_t bh0 = __float_as_uint(B_hi[bb]);
                const uint32_t bh1 = __float_as_uint(B_hi[bb + 4]);
                const uint32_t bl0 = __float_as_uint(B_lo[bb]);
                const uint32_t bl1 = __float_as_uint(B_lo[bb + 4]);
                #pragma unroll
                for (int mt = 0; mt < 2; ++mt) {
                    mma_tf32(c[mt][nt], ah[mt][0], ah[mt][1], ah[mt][2], ah[mt][3], bh0, bh1);
                    mma_tf32(c[mt][nt], ah[mt][0], ah[mt][1], ah[mt][2], ah[mt][3], bl0, bl1);
                    mma_tf32(c[mt][nt], al[mt][0], al[mt][1], al[mt][2], al[mt][3], bh0, bh1);
                }
            }
        }
        __syncthreads();
    }

    #pragma unroll
    for (int mt = 0; mt < 2; ++mt) {
        const int r_lo = u0 + wr * 32 + mt * 16 + l4;
        const float bv0 = __ldg(bi + r_lo);
        const float bv1 = __ldg(bi + r_lo + 8);
        const size_t G0 = (size_t)gate * HH + r_lo;
        #pragma unroll
        for (int nt = 0; nt < 4; ++nt) {
            const int bcol = wc * 32 + nt * 8 + lq * 2;
            float* p0 = g_xg + ((size_t)t * GH + G0) * BB + bcol;
            float* p1 = g_xg + ((size_t)t * GH + G0 + 8) * BB + bcol;
            *(float2*)p0 = make_float2(c[mt][nt][0] + bv0, c[mt][nt][1] + bv0);
            *(float2*)p1 = make_float2(c[mt][nt][2] + bv1, c[mt][nt][3] + bv1);
        }
    }
}

// ---------------------------------------------------------------------------
// Kernel 2: persistent recurrence with bf16x4 tensor-core step GEMM.
// Block owns 16 gate-rows (4 units x 4 gates), m16. 8 warps x n8 batch tiles,
// full K=512 per warp -> accumulate in regs, no cross-warp reduction.
// Cell state: 1 register per lane. h exchanged as bf16 hi/lo global planes.
// ---------------------------------------------------------------------------
__global__ void __launch_bounds__(256, 1) lstm_rec(
    const float* __restrict__ Wh0, const float* __restrict__ Wh1,
    const float* __restrict__ Wh2, const float* __restrict__ Wh3,
    const float* __restrict__ bh0, const float* __restrict__ bh1,
    const float* __restrict__ bh2, const float* __restrict__ bh3,
    float* __restrict__ out)
{
    extern __shared__ __align__(16) char smraw[];
    __nv_bfloat16* W_hi = (__nv_bfloat16*)smraw;              // [16][HS]
    __nv_bfloat16* W_lo = W_hi + 16 * HS;                     // [16][HS]
    __nv_bfloat16* h_hi = W_lo + 16 * HS;                     // [64][HS]
    __nv_bfloat16* h_lo = h_hi + 64 * HS;                     // [64][HS]

    const int tid  = threadIdx.x;
    const int wid  = tid >> 5;
    const int lane = tid & 31;
    const int l4   = lane >> 2;
    const int lq   = lane & 3;
    const int j0   = blockIdx.x * 4;

    // Pointwise identity of this lane (after the shfl exchange):
    const int u    = l4 & 3;
    const int bcol = wid * 8 + 2 * lq + (l4 >> 2);
    const bool lowHalf = (l4 < 4);

    // Preload W slice split into bf16 hi/lo: rows r = gate*4 + u
    for (int idx = tid; idx < 8192; idx += 256) {
        const int r = idx >> 9;      // 0..15
        const int k = idx & 511;
        const int gate = r >> 2, uu = r & 3;
        const float* W = gate == 0 ? Wh0 : gate == 1 ? Wh1 : gate == 2 ? Wh2 : Wh3;
        const float w = W[(size_t)(j0 + uu) * HH + k];
        const __nv_bfloat16 hi = __float2bfloat16(w);
        const __nv_bfloat16 lo = __float2bfloat16(w - __bfloat162float(hi));
        W_hi[r * HS + k] = hi;
        W_lo[r * HS + k] = lo;
    }
    // Zero h planes (h(-1) = 0): 2 * 64*HS bf16
    for (int idx = tid; idx < 64 * HS; idx += 256) {
        h_hi[idx] = __float2bfloat16(0.f);
        h_lo[idx] = __float2bfloat16(0.f);
    }
    // Per-lane hidden biases (4 gates at this lane's u)
    float bh_r[4];
    bh_r[0] = __ldg(bh0 + j0 + u);
    bh_r[1] = __ldg(bh1 + j0 + u);
    bh_r[2] = __ldg(bh2 + j0 + u);
    bh_r[3] = __ldg(bh3 + j0 + u);
    float c_reg = 0.f;
    __syncthreads();

    // Fragment base offsets (uint32 units; row stride = HS/2 = 260 words)
    const uint32_t* W32h = (const uint32_t*)W_hi;
    const uint32_t* W32l = (const uint32_t*)W_lo;
    const uint32_t* H32h = (const uint32_t*)h_hi;
    const uint32_t* H32l = (const uint32_t*)h_lo;
    const int aw0 = l4 * 260 + lq;
    const int aw1 = (l4 + 8) * 260 + lq;
    const int bw  = (wid * 8 + l4) * 260 + lq;

    #pragma unroll 1
    for (int t = 0; t < SS; ++t) {
        // Prefetch x-side gate preacts for this lane (independent of h)
        float xg_r[4];
        {
            const float* xgp = g_xg + (size_t)t * GH * BB;
            #pragma unroll
            for (int gate = 0; gate < 4; ++gate)
                xg_r[gate] = __ldg(xgp + (size_t)(gate * HH + j0 + u) * BB + bcol);
        }

        if (t > 0) {
            // Copy fresh h planes (bf16 hi/lo) into smem; row n: 512 bf16 = 64 uint4
            const int buf = (t - 1) & 1;
            const uint4* srcH = (const uint4*)g_hb[buf][0];
            const uint4* srcL = (const uint4*)g_hb[buf][1];
            for (int idx = tid; idx < 4096; idx += 256) {
                const int n = idx >> 6, q = idx & 63;
                const uint4 vh = __ldcg(srcH + idx);
                const uint4 vl = __ldcg(srcL + idx);
                *(uint4*)((char*)h_hi + n * (HS * 2) + q * 16) = vh;
                *(uint4*)((char*)h_lo + n * (HS * 2) + q * 16) = vl;
            }
            __syncthreads();
        }

        // MMA: c[m16 x n8] over K=512 in 32 k16 tiles, 4 split terms each
        float c[4] = {0.f, 0.f, 0.f, 0.f};
        #pragma unroll 4
        for (int kt = 0; kt < 32; ++kt) {
            const int ko = kt * 8;
            const uint32_t a0h = W32h[aw0 + ko],     a1h = W32h[aw1 + ko];
            const uint32_t a2h = W32h[aw0 + ko + 4], a3h = W32h[aw1 + ko + 4];
            const uint32_t a0l = W32l[aw0 + ko],     a1l = W32l[aw1 + ko];
            const uint32_t a2l = W32l[aw0 + ko + 4], a3l = W32l[aw1 + ko + 4];
            const uint32_t b0h = H32h[bw + ko], b1h = H32h[bw + ko + 4];
            const uint32_t b0l = H32l[bw + ko], b1l = H32l[bw + ko + 4];
            mma_bf16(c, a0h, a1h, a2h, a3h, b0h, b1h);
            mma_bf16(c, a0h, a1h, a2h, a3h, b0l, b1l);
            mma_bf16(c, a0l, a1l, a2l, a3l, b0h, b1h);
            mma_bf16(c, a0l, a1l, a2l, a3l, b0l, b1l);
        }

        // Regroup: lane pair (l4, l4 xor 4) swap so each lane holds all 4 gates
        // for (u, bcol). C frag: c0=(m=l4, n=2lq), c1=(m=l4, n=2lq+1),
        // c2=(m=l4+8, n=2lq), c3=(m=l4+8, n=2lq+1).
        float X = lowHalf ? c[1] : c[0];
        float Y = lowHalf ? c[3] : c[2];
        X = __shfl_xor_sync(0xffffffffu, X, 16);
        Y = __shfl_xor_sync(0xffffffffu, Y, 16);
        const float g0 = lowHalf ? c[0] : X;
        const float g1 = lowHalf ? X    : c[1];
        const float g2 = lowHalf ? c[2] : Y;
        const float g3 = lowHalf ? Y    : c[3];

        const float p0 = g0 + xg_r[0] + bh_r[0];
        const float p1 = g1 + xg_r[1] + bh_r[1];
        const float p2 = g2 + xg_r[2] + bh_r[2];
        const float p3 = g3 + xg_r[3] + bh_r[3];
        const float ig = 1.f / (1.f + expf(-p0));
        const float fg = 1.f / (1.f + expf(-p1));
        const float gg = tanhf(p2);
        const float og = 1.f / (1.f + expf(-p3));
        c_reg = fg * c_reg + ig * gg;
        const float hv = og * tanhf(c_reg);

        // Write h: bf16 hi/lo planes (for broadcast) + f32 output
        {
            const __nv_bfloat16 hhi = __float2bfloat16(hv);
            const __nv_bfloat16 hlo = __float2bfloat16(hv - __bfloat162float(hhi));
            const int hidx = bcol * 512 + j0 + u;
            g_hb[t & 1][0][hidx] = hhi;
            g_hb[t & 1][1][hidx] = hlo;
        }
        out[((size_t)bcol * SS + t) * HH + j0 + u] = hv;
        if (t == SS - 1) {
            out[(size_t)BB * SS * HH + (size_t)bcol * HH + j0 + u] = hv;
            out[(size_t)BB * SS * HH + (size_t)BB * HH + (size_t)bcol * HH + j0 + u] = c_reg;
        }

        // Grid barrier (monotonic counter)
        __threadfence();
        __syncthreads();
        if (tid == 0) {
            atomicAdd(&g_bar, 1u);
            const unsigned tgt = (unsigned)NB * (unsigned)(t + 1);
            while (*(volatile unsigned*)&g_bar < tgt) { }
        }
        __syncthreads();
    }
}

extern "C" void kernel_launch(void* const* d_in, const int* in_sizes, int n_in,
                              void* d_out, int out_size)
{
    // Classify inputs by element count — robust to metadata ordering.
    const float* x = (const float*)d_in[0];
    const float* Wi[4] = {0, 0, 0, 0};   // ii, if_, ig, io
    const float* Wh[4] = {0, 0, 0, 0};   // hi, hf, hg, ho
    const float* bv[8] = {0, 0, 0, 0, 0, 0, 0, 0}; // ii,hi,if_,hf,ig,hg,io,ho
    int nwi = 0, nwh = 0, nb = 0;
    for (int i = 1; i < n_in; ++i) {
        const int sz = in_sizes[i];
        if (sz == HH * II)      { if (nwi < 4) Wi[nwi++] = (const float*)d_in[i]; }
        else if (sz == HH * HH) { if (nwh < 4) Wh[nwh++] = (const float*)d_in[i]; }
        else if (sz == HH)      { if (nb  < 8) bv[nb++]  = (const float*)d_in[i]; }
    }
    const float* bii = bv[0];
    const float* bhi = bv[1];
    const float* bif = bv[2];
    const float* bhf = bv[3];
    const float* big = bv[4];
    const float* bhg = bv[5];
    const float* bio = bv[6];
    const float* bho = bv[7];
    float* out = (float*)d_out;

    const int gemm_smem = (2 * 128 * AST + 2 * 64 * AST) * 4;   // 101,376 B
    const int rec_smem  = (2 * 16 * HS + 2 * 64 * HS) * 2;      // 166,400 B
    cudaFuncSetAttribute(gemm_in_mma, cudaFuncAttributeMaxDynamicSharedMemorySize, gemm_smem);
    cudaFuncSetAttribute(lstm_rec,    cudaFuncAttributeMaxDynamicSharedMemorySize, rec_smem);

    dim3 g1(16, SS);
    gemm_in_mma<<<g1, 256, gemm_smem>>>(x, Wi[0], Wi[1], Wi[2], Wi[3], bii, bif, big, bio);
    reset_bar_k<<<1, 1>>>();
    lstm_rec<<<NB, 256, rec_smem>>>(Wh[0], Wh[1], Wh[2], Wh[3], bhi, bhf, bhg, bho, out);
}